// round 12
// baseline (speedup 1.0000x reference)
#include <cuda_runtime.h>
#include <cstdint>

// TreeNLLLoss, single fused kernel (R3 skeleton):
//   loss = sum_e edge_pot[e,16tc+tp] + sum_e unary[child_e,tc] + unary[root,l_root]
//   out  = -(loss - partition)
// E = 1,000,000, N = 1,000,001, C = 16.
//
// Round-11 change: exploit CROSS-REPLAY L2 reuse. The same 128 MB of
// edge_pot lines is touched every graph replay. A fractional evict_last
// policy pins a deterministic per-line-hash subset:
//   edge_pot: 75% evict_last / 25% evict_first  (~96 MB sticky, 32 MB/replay miss)
//   unary:    25% evict_last / 75% evict_first  (~16 MB sticky)
//   labels/idx: evict_normal (outranks evict_first -> stays hot)
// Warm DRAM ~136 MB -> ~80 MB.

#define C 16
#define EPT 8
#define THREADS 256
#define MAX_BLOCKS 4096

__device__ float    g_partials[MAX_BLOCKS];
__device__ unsigned g_count = 0;   // returns to 0 each replay (last block resets)

__device__ __forceinline__ uint64_t make_policy_75()
{
    uint64_t pol;
    asm("createpolicy.fractional.L2::evict_last.L2::evict_first.b64 %0, 0.75;"
        : "=l"(pol));
    return pol;
}

__device__ __forceinline__ uint64_t make_policy_25()
{
    uint64_t pol;
    asm("createpolicy.fractional.L2::evict_last.L2::evict_first.b64 %0, 0.25;"
        : "=l"(pol));
    return pol;
}

__device__ __forceinline__ float ld_pol_f32(const float* p, uint64_t pol)
{
    float v;
    asm("ld.global.nc.L2::cache_hint.f32 %0, [%1], %2;"
        : "=f"(v) : "l"(p), "l"(pol));
    return v;
}

__global__ void __launch_bounds__(THREADS)
fused_kernel(const float* __restrict__ edge_pot,
             const float* __restrict__ unary,
             const int*   __restrict__ labels,
             const int*   __restrict__ child_idx,
             const int*   __restrict__ parent_idx,
             const int*   __restrict__ root_idx,
             const float* __restrict__ partition,
             float* __restrict__ out,
             int E)
{
    const int tid  = blockIdx.x * THREADS + threadIdx.x;
    const int base = tid * EPT;
    const uint64_t pol_e = make_policy_75();
    const uint64_t pol_u = make_policy_25();

    float s = 0.0f;

    if (base + EPT <= E) {
        // Level 0: coalesced index streams (evict_normal -> stays hot in L2)
        int4 c4a = __ldg((const int4*)child_idx  + 2 * tid);
        int4 c4b = __ldg((const int4*)child_idx  + 2 * tid + 1);
        int4 p4a = __ldg((const int4*)parent_idx + 2 * tid);
        int4 p4b = __ldg((const int4*)parent_idx + 2 * tid + 1);
        int c[EPT] = {c4a.x, c4a.y, c4a.z, c4a.w, c4b.x, c4b.y, c4b.z, c4b.w};
        int p[EPT] = {p4a.x, p4a.y, p4a.z, p4a.w, p4b.x, p4b.y, p4b.z, p4b.w};

        // Level 1: label gathers (4 MB, evict_normal, L2-resident, MLP=16)
        int tc[EPT], tp[EPT];
        #pragma unroll
        for (int j = 0; j < EPT; j++) {
            tc[j] = __ldg(&labels[c[j]]);
            tp[j] = __ldg(&labels[p[j]]);
        }

        // Level 2: potential gathers (MLP=16), fractional evict_last pinning
        float ep[EPT], cu[EPT];
        #pragma unroll
        for (int j = 0; j < EPT; j++) {
            ep[j] = ld_pol_f32(&edge_pot[(size_t)(base + j) * (C * C) + tc[j] * C + tp[j]], pol_e);
            cu[j] = ld_pol_f32(&unary[(size_t)c[j] * C + tc[j]], pol_u);
        }

        #pragma unroll
        for (int j = 0; j < EPT; j++) s += ep[j] + cu[j];
    } else {
        // tail (unused for E = 1e6, kept for safety)
        for (int j = 0; j < EPT; j++) {
            int e = base + j;
            if (e < E) {
                int ci = __ldg(&child_idx[e]);
                int pi = __ldg(&parent_idx[e]);
                int tc = __ldg(&labels[ci]);
                int tp = __ldg(&labels[pi]);
                s += ld_pol_f32(&edge_pot[(size_t)e * (C * C) + tc * C + tp], pol_e);
                s += ld_pol_f32(&unary[(size_t)ci * C + tc], pol_u);
            }
        }
    }

    // ── block reduce (warp shuffle -> shared -> warp 0) ──
    #pragma unroll
    for (int off = 16; off > 0; off >>= 1)
        s += __shfl_down_sync(0xffffffffu, s, off);

    __shared__ float warp_sums[THREADS / 32];
    const int lane = threadIdx.x & 31;
    const int wid  = threadIdx.x >> 5;
    if (lane == 0) warp_sums[wid] = s;
    __syncthreads();

    if (wid == 0) {
        float t = (lane < THREADS / 32) ? warp_sums[lane] : 0.0f;
        #pragma unroll
        for (int off = 4; off > 0; off >>= 1)
            t += __shfl_down_sync(0xffffffffu, t, off);
        if (lane == 0) g_partials[blockIdx.x] = t;
    }

    // ── last-block-done finalize ──
    __shared__ bool is_last;
    __threadfence();
    if (threadIdx.x == 0) {
        unsigned ticket = atomicAdd(&g_count, 1u);
        is_last = (ticket == gridDim.x - 1);
    }
    __syncthreads();

    if (is_last) {
        double acc = 0.0;
        for (int i = threadIdx.x; i < (int)gridDim.x; i += THREADS)
            acc += (double)__ldcg(&g_partials[i]);

        #pragma unroll
        for (int off = 16; off > 0; off >>= 1)
            acc += __shfl_down_sync(0xffffffffu, acc, off);

        __shared__ double dwarp[THREADS / 32];
        if (lane == 0) dwarp[wid] = acc;
        __syncthreads();

        if (wid == 0) {
            double t = (lane < THREADS / 32) ? dwarp[lane] : 0.0;
            #pragma unroll
            for (int off = 4; off > 0; off >>= 1)
                t += __shfl_down_sync(0xffffffffu, t, off);
            if (lane == 0) {
                int r = __ldg(root_idx);
                float root_unary = __ldg(&unary[(size_t)r * C + __ldg(&labels[r])]);
                double loss = t + (double)root_unary;
                out[0] = -(float)(loss - (double)__ldg(partition));
                g_count = 0;   // reset for next replay
            }
        }
    }
}

extern "C" void kernel_launch(void* const* d_in, const int* in_sizes, int n_in,
                              void* d_out, int out_size)
{
    const float* edge_pot   = (const float*)d_in[0];
    const float* unary      = (const float*)d_in[1];
    const int*   labels     = (const int*)d_in[2];
    const int*   child_idx  = (const int*)d_in[3];
    const int*   parent_idx = (const int*)d_in[4];
    const int*   root_idx   = (const int*)d_in[5];
    const float* partition  = (const float*)d_in[6];
    float* out = (float*)d_out;

    int E = in_sizes[3];

    int per_block = THREADS * EPT;
    int blocks = (E + per_block - 1) / per_block;
    if (blocks > MAX_BLOCKS) blocks = MAX_BLOCKS;  // E=1e6 -> 489

    fused_kernel<<<blocks, THREADS>>>(edge_pot, unary, labels, child_idx,
                                      parent_idx, root_idx, partition, out, E);
}

// round 13
// speedup vs baseline: 1.2899x; 1.2899x over previous
#include <cuda_runtime.h>

// TreeNLLLoss, single fused kernel (R3 skeleton, best=36.4us):
//   loss = sum_e edge_pot[e,16tc+tp] + sum_e unary[child_e,tc] + unary[root,l_root]
//   out  = -(loss - partition)
// E = 1,000,000, N = 1,000,001, C = 16.
//
// Round-12 change: request 64B L2 fetch granularity (.L2::64B prefetch_size)
// on the two random gathers. Default LDG miss fills 128B/gather (measured:
// cold traffic decodes exactly as 128B per touched line). 4B of each 128B is
// used. If the hint controls fill width, edge_pot fills drop 128->64MB and
// unary ~60->~30MB per replay.

#define C 16
#define EPT 8
#define THREADS 256
#define MAX_BLOCKS 4096

__device__ float    g_partials[MAX_BLOCKS];
__device__ unsigned g_count = 0;   // returns to 0 each replay (last block resets)

// edge_pot: evict-first (one-shot) + 64B fetch granularity
__device__ __forceinline__ float ld_cs_64B(const float* p)
{
    float v;
    asm("ld.global.cs.L2::64B.f32 %0, [%1];" : "=f"(v) : "l"(p));
    return v;
}

// unary: read-only cached + 64B fetch granularity (rows are exactly 64B)
__device__ __forceinline__ float ld_nc_64B(const float* p)
{
    float v;
    asm("ld.global.nc.L2::64B.f32 %0, [%1];" : "=f"(v) : "l"(p));
    return v;
}

__global__ void __launch_bounds__(THREADS)
fused_kernel(const float* __restrict__ edge_pot,
             const float* __restrict__ unary,
             const int*   __restrict__ labels,
             const int*   __restrict__ child_idx,
             const int*   __restrict__ parent_idx,
             const int*   __restrict__ root_idx,
             const float* __restrict__ partition,
             float* __restrict__ out,
             int E)
{
    const int tid  = blockIdx.x * THREADS + threadIdx.x;
    const int base = tid * EPT;

    float s = 0.0f;

    if (base + EPT <= E) {
        // Level 0: coalesced index streams (two int4 per array)
        int4 c4a = __ldg((const int4*)child_idx  + 2 * tid);
        int4 c4b = __ldg((const int4*)child_idx  + 2 * tid + 1);
        int4 p4a = __ldg((const int4*)parent_idx + 2 * tid);
        int4 p4b = __ldg((const int4*)parent_idx + 2 * tid + 1);
        int c[EPT] = {c4a.x, c4a.y, c4a.z, c4a.w, c4b.x, c4b.y, c4b.z, c4b.w};
        int p[EPT] = {p4a.x, p4a.y, p4a.z, p4a.w, p4b.x, p4b.y, p4b.z, p4b.w};

        // Level 1: label gathers (4 MB, L2-resident, batched -> MLP=16)
        int tc[EPT], tp[EPT];
        #pragma unroll
        for (int j = 0; j < EPT; j++) {
            tc[j] = __ldg(&labels[c[j]]);
            tp[j] = __ldg(&labels[p[j]]);
        }

        // Level 2: potential gathers (MLP=16) with 64B fill granularity
        float ep[EPT], cu[EPT];
        #pragma unroll
        for (int j = 0; j < EPT; j++) {
            ep[j] = ld_cs_64B(&edge_pot[(size_t)(base + j) * (C * C) + tc[j] * C + tp[j]]);
            cu[j] = ld_nc_64B(&unary[(size_t)c[j] * C + tc[j]]);
        }

        #pragma unroll
        for (int j = 0; j < EPT; j++) s += ep[j] + cu[j];
    } else {
        // tail (unused for E = 1e6, kept for safety)
        for (int j = 0; j < EPT; j++) {
            int e = base + j;
            if (e < E) {
                int ci = __ldg(&child_idx[e]);
                int pi = __ldg(&parent_idx[e]);
                int tc = __ldg(&labels[ci]);
                int tp = __ldg(&labels[pi]);
                s += ld_cs_64B(&edge_pot[(size_t)e * (C * C) + tc * C + tp]);
                s += ld_nc_64B(&unary[(size_t)ci * C + tc]);
            }
        }
    }

    // ── block reduce (warp shuffle -> shared -> warp 0) ──
    #pragma unroll
    for (int off = 16; off > 0; off >>= 1)
        s += __shfl_down_sync(0xffffffffu, s, off);

    __shared__ float warp_sums[THREADS / 32];
    const int lane = threadIdx.x & 31;
    const int wid  = threadIdx.x >> 5;
    if (lane == 0) warp_sums[wid] = s;
    __syncthreads();

    if (wid == 0) {
        float t = (lane < THREADS / 32) ? warp_sums[lane] : 0.0f;
        #pragma unroll
        for (int off = 4; off > 0; off >>= 1)
            t += __shfl_down_sync(0xffffffffu, t, off);
        if (lane == 0) g_partials[blockIdx.x] = t;
    }

    // ── last-block-done finalize ──
    __shared__ bool is_last;
    __threadfence();
    if (threadIdx.x == 0) {
        unsigned ticket = atomicAdd(&g_count, 1u);
        is_last = (ticket == gridDim.x - 1);
    }
    __syncthreads();

    if (is_last) {
        double acc = 0.0;
        for (int i = threadIdx.x; i < (int)gridDim.x; i += THREADS)
            acc += (double)__ldcg(&g_partials[i]);

        #pragma unroll
        for (int off = 16; off > 0; off >>= 1)
            acc += __shfl_down_sync(0xffffffffu, acc, off);

        __shared__ double dwarp[THREADS / 32];
        if (lane == 0) dwarp[wid] = acc;
        __syncthreads();

        if (wid == 0) {
            double t = (lane < THREADS / 32) ? dwarp[lane] : 0.0;
            #pragma unroll
            for (int off = 4; off > 0; off >>= 1)
                t += __shfl_down_sync(0xffffffffu, t, off);
            if (lane == 0) {
                int r = __ldg(root_idx);
                float root_unary = __ldg(&unary[(size_t)r * C + __ldg(&labels[r])]);
                double loss = t + (double)root_unary;
                out[0] = -(float)(loss - (double)__ldg(partition));
                g_count = 0;   // reset for next replay
            }
        }
    }
}

extern "C" void kernel_launch(void* const* d_in, const int* in_sizes, int n_in,
                              void* d_out, int out_size)
{
    const float* edge_pot   = (const float*)d_in[0];
    const float* unary      = (const float*)d_in[1];
    const int*   labels     = (const int*)d_in[2];
    const int*   child_idx  = (const int*)d_in[3];
    const int*   parent_idx = (const int*)d_in[4];
    const int*   root_idx   = (const int*)d_in[5];
    const float* partition  = (const float*)d_in[6];
    float* out = (float*)d_out;

    int E = in_sizes[3];

    int per_block = THREADS * EPT;
    int blocks = (E + per_block - 1) / per_block;
    if (blocks > MAX_BLOCKS) blocks = MAX_BLOCKS;  // E=1e6 -> 489

    fused_kernel<<<blocks, THREADS>>>(edge_pot, unary, labels, child_idx,
                                      parent_idx, root_idx, partition, out, E);
}

// round 14
// speedup vs baseline: 1.3588x; 1.0534x over previous
#include <cuda_runtime.h>

// TreeNLLLoss, single fused kernel:
//   loss = sum_e edge_pot[e,16tc+tp] + sum_e unary[child_e,tc] + unary[root,l_root]
//   out  = -(loss - partition)
// E = 1,000,000, N = 1,000,001, C = 16.
//
// R13 established: .L2::64B fetch-granularity hints on the random gathers
// halve DRAM fill traffic (4479 -> 2526 GB/s) -> kernel is now LATENCY bound
// (DRAM 32%, issue 2%). R14 change: EPT 8 -> 4, doubling resident warps
// (26 -> 52/SM, occ 43% -> ~83%) to double in-flight misses.

#define C 16
#define EPT 4
#define THREADS 256
#define MAX_BLOCKS 4096

__device__ float    g_partials[MAX_BLOCKS];
__device__ unsigned g_count = 0;   // returns to 0 each replay (last block resets)

// edge_pot: evict-first (one-shot) + 64B fetch granularity
__device__ __forceinline__ float ld_cs_64B(const float* p)
{
    float v;
    asm("ld.global.cs.L2::64B.f32 %0, [%1];" : "=f"(v) : "l"(p));
    return v;
}

// unary: read-only cached + 64B fetch granularity (rows are exactly 64B)
__device__ __forceinline__ float ld_nc_64B(const float* p)
{
    float v;
    asm("ld.global.nc.L2::64B.f32 %0, [%1];" : "=f"(v) : "l"(p));
    return v;
}

__global__ void __launch_bounds__(THREADS)
fused_kernel(const float* __restrict__ edge_pot,
             const float* __restrict__ unary,
             const int*   __restrict__ labels,
             const int*   __restrict__ child_idx,
             const int*   __restrict__ parent_idx,
             const int*   __restrict__ root_idx,
             const float* __restrict__ partition,
             float* __restrict__ out,
             int E)
{
    const int tid  = blockIdx.x * THREADS + threadIdx.x;
    const int base = tid * EPT;

    float s = 0.0f;

    if (base + EPT <= E) {
        // Level 0: coalesced int4 index loads
        int4 c4 = __ldg((const int4*)child_idx  + tid);
        int4 p4 = __ldg((const int4*)parent_idx + tid);
        int c[EPT] = {c4.x, c4.y, c4.z, c4.w};
        int p[EPT] = {p4.x, p4.y, p4.z, p4.w};

        // Level 1: label gathers (4 MB, L2-resident, batched -> MLP=8)
        int tc[EPT], tp[EPT];
        #pragma unroll
        for (int j = 0; j < EPT; j++) {
            tc[j] = __ldg(&labels[c[j]]);
            tp[j] = __ldg(&labels[p[j]]);
        }

        // Level 2: potential gathers (MLP=8) with 64B fill granularity
        float ep[EPT], cu[EPT];
        #pragma unroll
        for (int j = 0; j < EPT; j++) {
            ep[j] = ld_cs_64B(&edge_pot[(size_t)(base + j) * (C * C) + tc[j] * C + tp[j]]);
            cu[j] = ld_nc_64B(&unary[(size_t)c[j] * C + tc[j]]);
        }

        #pragma unroll
        for (int j = 0; j < EPT; j++) s += ep[j] + cu[j];
    } else {
        // tail (unused for E = 1e6, kept for safety)
        for (int j = 0; j < EPT; j++) {
            int e = base + j;
            if (e < E) {
                int ci = __ldg(&child_idx[e]);
                int pi = __ldg(&parent_idx[e]);
                int tc = __ldg(&labels[ci]);
                int tp = __ldg(&labels[pi]);
                s += ld_cs_64B(&edge_pot[(size_t)e * (C * C) + tc * C + tp]);
                s += ld_nc_64B(&unary[(size_t)ci * C + tc]);
            }
        }
    }

    // ── block reduce (warp shuffle -> shared -> warp 0) ──
    #pragma unroll
    for (int off = 16; off > 0; off >>= 1)
        s += __shfl_down_sync(0xffffffffu, s, off);

    __shared__ float warp_sums[THREADS / 32];
    const int lane = threadIdx.x & 31;
    const int wid  = threadIdx.x >> 5;
    if (lane == 0) warp_sums[wid] = s;
    __syncthreads();

    if (wid == 0) {
        float t = (lane < THREADS / 32) ? warp_sums[lane] : 0.0f;
        #pragma unroll
        for (int off = 4; off > 0; off >>= 1)
            t += __shfl_down_sync(0xffffffffu, t, off);
        if (lane == 0) g_partials[blockIdx.x] = t;
    }

    // ── last-block-done finalize ──
    __shared__ bool is_last;
    __threadfence();
    if (threadIdx.x == 0) {
        unsigned ticket = atomicAdd(&g_count, 1u);
        is_last = (ticket == gridDim.x - 1);
    }
    __syncthreads();

    if (is_last) {
        double acc = 0.0;
        for (int i = threadIdx.x; i < (int)gridDim.x; i += THREADS)
            acc += (double)__ldcg(&g_partials[i]);

        #pragma unroll
        for (int off = 16; off > 0; off >>= 1)
            acc += __shfl_down_sync(0xffffffffu, acc, off);

        __shared__ double dwarp[THREADS / 32];
        if (lane == 0) dwarp[wid] = acc;
        __syncthreads();

        if (wid == 0) {
            double t = (lane < THREADS / 32) ? dwarp[lane] : 0.0;
            #pragma unroll
            for (int off = 4; off > 0; off >>= 1)
                t += __shfl_down_sync(0xffffffffu, t, off);
            if (lane == 0) {
                int r = __ldg(root_idx);
                float root_unary = __ldg(&unary[(size_t)r * C + __ldg(&labels[r])]);
                double loss = t + (double)root_unary;
                out[0] = -(float)(loss - (double)__ldg(partition));
                g_count = 0;   // reset for next replay
            }
        }
    }
}

extern "C" void kernel_launch(void* const* d_in, const int* in_sizes, int n_in,
                              void* d_out, int out_size)
{
    const float* edge_pot   = (const float*)d_in[0];
    const float* unary      = (const float*)d_in[1];
    const int*   labels     = (const int*)d_in[2];
    const int*   child_idx  = (const int*)d_in[3];
    const int*   parent_idx = (const int*)d_in[4];
    const int*   root_idx   = (const int*)d_in[5];
    const float* partition  = (const float*)d_in[6];
    float* out = (float*)d_out;

    int E = in_sizes[3];

    int per_block = THREADS * EPT;
    int blocks = (E + per_block - 1) / per_block;
    if (blocks > MAX_BLOCKS) blocks = MAX_BLOCKS;  // E=1e6 -> 977

    fused_kernel<<<blocks, THREADS>>>(edge_pot, unary, labels, child_idx,
                                      parent_idx, root_idx, partition, out, E);
}

// round 15
// speedup vs baseline: 1.3692x; 1.0077x over previous
#include <cuda_runtime.h>
#include <cstdint>

// TreeNLLLoss, two kernels per replay.
// R14 finding: kernel sits exactly on the L1tex wavefront floor
// (4 random 4B gathers/edge x 2.07 cyc/wf = measured 33.5us). This round
// cuts random wavefronts 4 -> 3 per edge:
//   A) node_sweep: rec8[v] = {unary[v,labels[v]], labels[v]}  (8 MB).
//      Sequential-v access => unary read is stride-64B (0.5 wf/node, cheap).
//   B) edge_kernel: per edge only 3 random gathers:
//      rec8[child] (unary val + tc in ONE 8B gather), rec8[parent] (tp),
//      edge_pot[e,16tc+tp] with .L2::64B fill hint.
//   loss = sum_e ep + sum_e val_child + val_root;  out = -(loss - partition)
// E = 1,000,000, N = 1,000,001, C = 16.

#define C 16
#define EPT 4
#define THREADS 256
#define MAX_BLOCKS 4096
#define N_MAX 1000960

__device__ uint2    g_rec[N_MAX];          // {f32 val bits, label}
__device__ float    g_partials[MAX_BLOCKS];
__device__ unsigned g_count = 0;           // returns to 0 each replay

// edge_pot: evict-first + 64B fetch granularity (R13 win)
__device__ __forceinline__ float ld_cs_64B(const float* p)
{
    float v;
    asm("ld.global.cs.L2::64B.f32 %0, [%1];" : "=f"(v) : "l"(p));
    return v;
}

// ── Kernel A: node sweep. Block b covers nodes [b*1024, b*1024+1024).
// Lane-consecutive node mapping => unary gather is 64B-strided (nL=16/LDG).
__global__ void __launch_bounds__(THREADS)
node_sweep(const float* __restrict__ unary,
           const int*   __restrict__ labels,
           int N)
{
    const int block_base = blockIdx.x * (THREADS * 4);
    #pragma unroll
    for (int j = 0; j < 4; j++) {
        int v = block_base + j * THREADS + threadIdx.x;   // consecutive per lane
        if (v < N) {
            int lab = __ldg(&labels[v]);
            float val = __ldg(&unary[(size_t)v * C + lab]);
            uint2 r;
            r.x = __float_as_uint(val);
            r.y = (unsigned)lab;
            g_rec[v] = r;
        }
    }
}

// ── Kernel B: edge gathers (3 random wf/edge) + reduce + finalize ──
__global__ void __launch_bounds__(THREADS)
edge_kernel(const float* __restrict__ edge_pot,
            const int*   __restrict__ child_idx,
            const int*   __restrict__ parent_idx,
            const int*   __restrict__ root_idx,
            const float* __restrict__ partition,
            float* __restrict__ out,
            int E)
{
    const int tid  = blockIdx.x * THREADS + threadIdx.x;
    const int base = tid * EPT;

    float s = 0.0f;

    if (base + EPT <= E) {
        // coalesced index streams
        int4 c4 = __ldg((const int4*)child_idx  + tid);
        int4 p4 = __ldg((const int4*)parent_idx + tid);
        int c[EPT] = {c4.x, c4.y, c4.z, c4.w};
        int p[EPT] = {p4.x, p4.y, p4.z, p4.w};

        // child record: unary value + child label in ONE gather
        uint2 rc[EPT];
        #pragma unroll
        for (int j = 0; j < EPT; j++)
            rc[j] = __ldg(&g_rec[c[j]]);

        // parent label only (4B from the record's .y)
        unsigned tp[EPT];
        #pragma unroll
        for (int j = 0; j < EPT; j++)
            tp[j] = __ldg(&((const unsigned*)g_rec)[2 * p[j] + 1]);

        // edge potential gather (64B fill)
        float ep[EPT];
        #pragma unroll
        for (int j = 0; j < EPT; j++)
            ep[j] = ld_cs_64B(&edge_pot[(size_t)(base + j) * (C * C)
                                        + rc[j].y * C + tp[j]]);

        #pragma unroll
        for (int j = 0; j < EPT; j++)
            s += ep[j] + __uint_as_float(rc[j].x);
    } else {
        for (int j = 0; j < EPT; j++) {
            int e = base + j;
            if (e < E) {
                int ci = __ldg(&child_idx[e]);
                int pi = __ldg(&parent_idx[e]);
                uint2 rc = __ldg(&g_rec[ci]);
                unsigned tp = __ldg(&((const unsigned*)g_rec)[2 * pi + 1]);
                s += ld_cs_64B(&edge_pot[(size_t)e * (C * C) + rc.y * C + tp]);
                s += __uint_as_float(rc.x);
            }
        }
    }

    // ── block reduce ──
    #pragma unroll
    for (int off = 16; off > 0; off >>= 1)
        s += __shfl_down_sync(0xffffffffu, s, off);

    __shared__ float warp_sums[THREADS / 32];
    const int lane = threadIdx.x & 31;
    const int wid  = threadIdx.x >> 5;
    if (lane == 0) warp_sums[wid] = s;
    __syncthreads();

    if (wid == 0) {
        float t = (lane < THREADS / 32) ? warp_sums[lane] : 0.0f;
        #pragma unroll
        for (int off = 4; off > 0; off >>= 1)
            t += __shfl_down_sync(0xffffffffu, t, off);
        if (lane == 0) g_partials[blockIdx.x] = t;
    }

    // ── last-block-done finalize ──
    __shared__ bool is_last;
    __threadfence();
    if (threadIdx.x == 0) {
        unsigned ticket = atomicAdd(&g_count, 1u);
        is_last = (ticket == gridDim.x - 1);
    }
    __syncthreads();

    if (is_last) {
        double acc = 0.0;
        for (int i = threadIdx.x; i < (int)gridDim.x; i += THREADS)
            acc += (double)__ldcg(&g_partials[i]);

        #pragma unroll
        for (int off = 16; off > 0; off >>= 1)
            acc += __shfl_down_sync(0xffffffffu, acc, off);

        __shared__ double dwarp[THREADS / 32];
        if (lane == 0) dwarp[wid] = acc;
        __syncthreads();

        if (wid == 0) {
            double t = (lane < THREADS / 32) ? dwarp[lane] : 0.0;
            #pragma unroll
            for (int off = 4; off > 0; off >>= 1)
                t += __shfl_down_sync(0xffffffffu, t, off);
            if (lane == 0) {
                int r = __ldg(root_idx);
                uint2 rr = g_rec[r];
                double loss = t + (double)__uint_as_float(rr.x);
                out[0] = -(float)(loss - (double)__ldg(partition));
                g_count = 0;   // reset for next replay
            }
        }
    }
}

extern "C" void kernel_launch(void* const* d_in, const int* in_sizes, int n_in,
                              void* d_out, int out_size)
{
    const float* edge_pot   = (const float*)d_in[0];
    const float* unary      = (const float*)d_in[1];
    const int*   labels     = (const int*)d_in[2];
    const int*   child_idx  = (const int*)d_in[3];
    const int*   parent_idx = (const int*)d_in[4];
    const int*   root_idx   = (const int*)d_in[5];
    const float* partition  = (const float*)d_in[6];
    float* out = (float*)d_out;

    int N = in_sizes[2];
    int E = in_sizes[3];

    int sweep_blocks = (N + THREADS * 4 - 1) / (THREADS * 4);   // 977
    node_sweep<<<sweep_blocks, THREADS>>>(unary, labels, N);

    int per_block = THREADS * EPT;
    int blocks = (E + per_block - 1) / per_block;
    if (blocks > MAX_BLOCKS) blocks = MAX_BLOCKS;               // 977

    edge_kernel<<<blocks, THREADS>>>(edge_pot, child_idx, parent_idx,
                                     root_idx, partition, out, E);
}